// round 1
// baseline (speedup 1.0000x reference)
#include <cuda_runtime.h>
#include <cstdint>

#define MODES 16
#define LOG2E 1.4426950408889634f
#define LN2   0.6931471805599453f
#define E_CONST 2.7182818284590452f

// Scratch for the cross-block column-min reduction (float encoded as orderable uint).
__device__ unsigned g_vmin_keys[MODES];

__device__ __forceinline__ unsigned float_to_key(float f) {
    unsigned u = __float_as_uint(f);
    return (u & 0x80000000u) ? ~u : (u ^ 0x80000000u);
}
__device__ __forceinline__ float key_to_float(unsigned k) {
    unsigned u = (k & 0x80000000u) ? (k ^ 0x80000000u) : ~k;
    return __uint_as_float(u);
}
__device__ __forceinline__ float ex2_approx(float x) {
    float r;
    asm("ex2.approx.f32 %0, %1;" : "=f"(r) : "f"(x));
    return r;
}
__device__ __forceinline__ float rcp_approx(float x) {
    float r;
    asm("rcp.approx.f32 %0, %1;" : "=f"(r) : "f"(x));
    return r;
}

__global__ void comp_init_kernel() {
    if (threadIdx.x < MODES) g_vmin_keys[threadIdx.x] = 0xFFFFFFFFu;
}

// Grid-stride per-column min over V[N, 16].
__global__ void comp_vmin_kernel(const float* __restrict__ V, int N) {
    float m[MODES];
#pragma unroll
    for (int j = 0; j < MODES; j++) m[j] = 3.4028235e38f;

    int stride = gridDim.x * blockDim.x;
    for (int r = blockIdx.x * blockDim.x + threadIdx.x; r < N; r += stride) {
        const float4* p = (const float4*)(V + (size_t)r * MODES);
#pragma unroll
        for (int q = 0; q < 4; q++) {
            float4 v = p[q];
            m[4 * q + 0] = fminf(m[4 * q + 0], v.x);
            m[4 * q + 1] = fminf(m[4 * q + 1], v.y);
            m[4 * q + 2] = fminf(m[4 * q + 2], v.z);
            m[4 * q + 3] = fminf(m[4 * q + 3], v.w);
        }
    }
    // warp butterfly reduce
#pragma unroll
    for (int off = 16; off; off >>= 1) {
#pragma unroll
        for (int j = 0; j < MODES; j++)
            m[j] = fminf(m[j], __shfl_xor_sync(0xFFFFFFFFu, m[j], off));
    }
    __shared__ unsigned smin[MODES];
    if (threadIdx.x < MODES) smin[threadIdx.x] = 0xFFFFFFFFu;
    __syncthreads();
    if ((threadIdx.x & 31) == 0) {
#pragma unroll
        for (int j = 0; j < MODES; j++)
            atomicMin(&smin[j], float_to_key(m[j]));
    }
    __syncthreads();
    if (threadIdx.x < MODES)
        atomicMin(&g_vmin_keys[threadIdx.x], smin[threadIdx.x]);
}

// One row per thread. phi -> pairwise power interpolation -> modal -> log_softmax.
__global__ void __launch_bounds__(256) comp_main_kernel(
    const float* __restrict__ V,
    const float* __restrict__ w,
    const float* __restrict__ b,
    const float* __restrict__ gammas,
    float* __restrict__ out, int N)
{
    __shared__ float Gs[MODES][MODES];
    __shared__ float sw[MODES], sb[MODES], svmin[MODES];
    int t = threadIdx.x;
    if (t < MODES * MODES) {
        int i = t >> 4, j = t & 15;
        float g = 0.0f;
        if (j > i)      g = gammas[i * MODES + j];
        else if (j < i) g = gammas[j * MODES + i];
        Gs[i][j] = g;
    }
    if (t < MODES) {
        sw[t] = 1.0f + w[t];
        sb[t] = b[t];
        svmin[t] = key_to_float(g_vmin_keys[t]);
    }
    __syncthreads();

    int r = blockIdx.x * blockDim.x + t;
    if (r >= N) return;

    float phi[MODES], L[MODES];
    {
        const float4* p = (const float4*)(V + (size_t)r * MODES);
#pragma unroll
        for (int q = 0; q < 4; q++) {
            float4 v = p[q];
            float vv[4] = {v.x, v.y, v.z, v.w};
#pragma unroll
            for (int k = 0; k < 4; k++) {
                int j = 4 * q + k;
                float vc = fmaxf(vv[k] - svmin[j] + E_CONST, E_CONST);
                float ph = fmaf(sw[j], vc, sb[j]);
                phi[j] = ph;
                L[j] = __log2f(ph);
            }
        }
    }

    // modal_i = phi_i + sum_{j!=i} 2^( G[i][j]*(L_i - L_j) + L_j )
    float x[MODES];
    const float tau = 0.25f;  // 1/sqrt(16)
    float xm = -3.4e38f;
#pragma unroll
    for (int i = 0; i < MODES; i++) {
        float acc = phi[i];
        float Li = L[i];
#pragma unroll
        for (int j = 0; j < MODES; j++) {
            if (j == i) continue;
            float g = Gs[i][j];
            float e = fmaf(g, Li - L[j], L[j]);
            acc += ex2_approx(e);
        }
        float xi = -tau * acc;
        x[i] = xi;
        xm = fmaxf(xm, xi);
    }

    // log_softmax over 16
    float ex[MODES];
    float s = 0.0f;
#pragma unroll
    for (int i = 0; i < MODES; i++) {
        float e2 = ex2_approx((x[i] - xm) * LOG2E);
        ex[i] = e2;
        s += e2;
    }
    float lns = __log2f(s) * LN2;
    float inv_s = rcp_approx(s);

    float av[MODES], lv[MODES];
#pragma unroll
    for (int i = 0; i < MODES; i++) {
        lv[i] = x[i] - xm - lns;
        av[i] = ex[i] * inv_s;
    }

    float* alpha_out = out + (size_t)r * MODES;
    float* logit_out = out + (size_t)N * MODES + (size_t)r * MODES;
#pragma unroll
    for (int q = 0; q < 4; q++) {
        ((float4*)alpha_out)[q] = make_float4(av[4*q], av[4*q+1], av[4*q+2], av[4*q+3]);
        ((float4*)logit_out)[q] = make_float4(lv[4*q], lv[4*q+1], lv[4*q+2], lv[4*q+3]);
    }
}

extern "C" void kernel_launch(void* const* d_in, const int* in_sizes, int n_in,
                              void* d_out, int out_size) {
    const float* V      = (const float*)d_in[0];
    const float* w      = (const float*)d_in[1];
    const float* b      = (const float*)d_in[2];
    const float* gammas = (const float*)d_in[3];
    float* out = (float*)d_out;
    int N = in_sizes[0] / MODES;

    comp_init_kernel<<<1, 32>>>();
    comp_vmin_kernel<<<592, 256>>>(V, N);
    int blocks = (N + 255) / 256;
    comp_main_kernel<<<blocks, 256>>>(V, w, b, gammas, out, N);
}

// round 2
// speedup vs baseline: 1.0808x; 1.0808x over previous
#include <cuda_runtime.h>
#include <cstdint>

#define MODES 16
#define LOG2E 1.4426950408889634f
#define LN2   0.6931471805599453f
#define E_CONST 2.7182818284590452f
#define TAU   0.25f   /* 1/sqrt(16) */

// Scratch for the cross-block column-min reduction (float encoded as orderable uint).
__device__ unsigned g_vmin_keys[MODES];

__device__ __forceinline__ unsigned float_to_key(float f) {
    unsigned u = __float_as_uint(f);
    return (u & 0x80000000u) ? ~u : (u ^ 0x80000000u);
}
__device__ __forceinline__ float key_to_float(unsigned k) {
    unsigned u = (k & 0x80000000u) ? (k ^ 0x80000000u) : ~k;
    return __uint_as_float(u);
}
__device__ __forceinline__ float ex2_approx(float x) {
    float r;
    asm("ex2.approx.f32 %0, %1;" : "=f"(r) : "f"(x));
    return r;
}
__device__ __forceinline__ float rcp_approx(float x) {
    float r;
    asm("rcp.approx.f32 %0, %1;" : "=f"(r) : "f"(x));
    return r;
}

// FMA/ALU-pipe exp2 (keeps MUFU free). Valid for |e| < ~120; here e in ~[1, 5].
// Range-reduce with the 1.5*2^23 magic constant, deg-5 poly on f in [-0.5, 0.5]
// (~2e-6 rel err), exponent applied via integer add into the float bits.
__device__ __forceinline__ float exp2_poly(float e) {
    float y = e + 12582912.0f;            // mantissa now holds round(e)
    float k = y - 12582912.0f;            // (float)round(e), exact
    float f = e - k;                      // f in [-0.5, 0.5]
    float p = fmaf(f, 0.00133335581f, 0.00961812911f);
    p = fmaf(f, p, 0.05550410866f);
    p = fmaf(f, p, 0.24022650696f);
    p = fmaf(f, p, 0.69314718056f);
    p = fmaf(f, p, 1.0f);
    unsigned kb = __float_as_uint(y) << 23;   // round(e) << 23 (low bits of magic are 0)
    return __uint_as_float(__float_as_uint(p) + kb);
}

__global__ void comp_init_kernel() {
    if (threadIdx.x < MODES) g_vmin_keys[threadIdx.x] = 0xFFFFFFFFu;
}

// Grid-stride per-column min over V[N, 16].
__global__ void comp_vmin_kernel(const float* __restrict__ V, int N) {
    float m[MODES];
#pragma unroll
    for (int j = 0; j < MODES; j++) m[j] = 3.4028235e38f;

    int stride = gridDim.x * blockDim.x;
    for (int r = blockIdx.x * blockDim.x + threadIdx.x; r < N; r += stride) {
        const float4* p = (const float4*)(V + (size_t)r * MODES);
#pragma unroll
        for (int q = 0; q < 4; q++) {
            float4 v = p[q];
            m[4 * q + 0] = fminf(m[4 * q + 0], v.x);
            m[4 * q + 1] = fminf(m[4 * q + 1], v.y);
            m[4 * q + 2] = fminf(m[4 * q + 2], v.z);
            m[4 * q + 3] = fminf(m[4 * q + 3], v.w);
        }
    }
#pragma unroll
    for (int off = 16; off; off >>= 1) {
#pragma unroll
        for (int j = 0; j < MODES; j++)
            m[j] = fminf(m[j], __shfl_xor_sync(0xFFFFFFFFu, m[j], off));
    }
    __shared__ unsigned smin[MODES];
    if (threadIdx.x < MODES) smin[threadIdx.x] = 0xFFFFFFFFu;
    __syncthreads();
    if ((threadIdx.x & 31) == 0) {
#pragma unroll
        for (int j = 0; j < MODES; j++)
            atomicMin(&smin[j], float_to_key(m[j]));
    }
    __syncthreads();
    if (threadIdx.x < MODES)
        atomicMin(&g_vmin_keys[threadIdx.x], smin[threadIdx.x]);
}

// One row per thread. phi -> pairwise power interpolation -> modal -> log_softmax.
// Register-lean restructure: phi dies into acc; per-pair both directions computed
// from one diff; softmax works on acc directly (tau folded); pairs with j-i>=11
// take the FMA-pipe polynomial exp2 to offload MUFU.
__global__ void __launch_bounds__(256) comp_main_kernel(
    const float* __restrict__ V,
    const float* __restrict__ w,
    const float* __restrict__ b,
    const float* __restrict__ gammas,
    float* __restrict__ out, int N)
{
    __shared__ float Gs[MODES][MODES];
    __shared__ float sw[MODES], sb[MODES], svmin[MODES];
    int t = threadIdx.x;
    if (t < MODES * MODES) {
        int i = t >> 4, j = t & 15;
        float g = 0.0f;
        if (j > i)      g = gammas[i * MODES + j];
        else if (j < i) g = gammas[j * MODES + i];
        Gs[i][j] = g;
    }
    if (t < MODES) {
        sw[t] = 1.0f + w[t];
        sb[t] = b[t];
        svmin[t] = key_to_float(g_vmin_keys[t]);
    }
    __syncthreads();

    int r = blockIdx.x * blockDim.x + t;
    if (r >= N) return;

    float acc[MODES], L[MODES];
    {
        const float4* p = (const float4*)(V + (size_t)r * MODES);
#pragma unroll
        for (int q = 0; q < 4; q++) {
            float4 v = p[q];
            float vv[4] = {v.x, v.y, v.z, v.w};
#pragma unroll
            for (int k = 0; k < 4; k++) {
                int j = 4 * q + k;
                float vc = fmaxf(vv[k] - svmin[j] + E_CONST, E_CONST);
                float ph = fmaf(sw[j], vc, sb[j]);
                acc[j] = ph;                 // diagonal term seeds the sum
                L[j] = __log2f(ph);
            }
        }
    }

    // acc_i += sum_{j != i} 2^( g*(L_i - L_j) + L_j ), exploiting e_ji = L_i - g*d.
#pragma unroll
    for (int i = 0; i < MODES; i++) {
#pragma unroll
        for (int j = i + 1; j < MODES; j++) {
            float g = Gs[i][j];
            float d = L[i] - L[j];
            float e1 = fmaf(g, d, L[j]);     // exponent of P[i][j]
            float e2 = fmaf(-g, d, L[i]);    // exponent of P[j][i]
            float p1, p2;
            if (j - i >= 11) {               // compile-time: poly path (FMA pipe)
                p1 = exp2_poly(e1);
                p2 = exp2_poly(e2);
            } else {                         // MUFU path
                p1 = ex2_approx(e1);
                p2 = ex2_approx(e2);
            }
            acc[i] += p1;
            acc[j] += p2;
        }
    }

    // log_softmax of x = -tau*acc, with tau folded in:
    // x_i - xmax = -tau*(acc_i - acc_min)
    float amin = acc[0];
#pragma unroll
    for (int i = 1; i < MODES; i++) amin = fminf(amin, acc[i]);

    const float nts = -TAU * LOG2E;          // scale for ex2
    float ex[MODES];
    float s = 0.0f;
#pragma unroll
    for (int i = 0; i < MODES; i++) {
        float e2 = ex2_approx((acc[i] - amin) * nts);
        ex[i] = e2;
        s += e2;
    }
    float lns = __log2f(s) * LN2;
    float inv_s = rcp_approx(s);

    float* alpha_out = out + (size_t)r * MODES;
    float* logit_out = out + (size_t)N * MODES + (size_t)r * MODES;
#pragma unroll
    for (int q = 0; q < 4; q++) {
        float4 a4, l4;
        float* ap = &a4.x;
        float* lp = &l4.x;
#pragma unroll
        for (int k = 0; k < 4; k++) {
            int i = 4 * q + k;
            ap[k] = ex[i] * inv_s;
            lp[k] = fmaf(-TAU, acc[i] - amin, -lns);
        }
        ((float4*)alpha_out)[q] = a4;
        ((float4*)logit_out)[q] = l4;
    }
}

extern "C" void kernel_launch(void* const* d_in, const int* in_sizes, int n_in,
                              void* d_out, int out_size) {
    const float* V      = (const float*)d_in[0];
    const float* w      = (const float*)d_in[1];
    const float* b      = (const float*)d_in[2];
    const float* gammas = (const float*)d_in[3];
    float* out = (float*)d_out;
    int N = in_sizes[0] / MODES;

    comp_init_kernel<<<1, 32>>>();
    comp_vmin_kernel<<<592, 256>>>(V, N);
    int blocks = (N + 255) / 256;
    comp_main_kernel<<<blocks, 256>>>(V, w, b, gammas, out, N);
}